// round 6
// baseline (speedup 1.0000x reference)
#include <cuda_runtime.h>
#include <cuda_bf16.h>

// AddingGaussianBlur: x (64,512,512,3) f32, stds (64,) f32 -> out f32.
//
// Separable (reference's 3x3 kernel depends only on column index):
//   vertical  : unweighted 3-row sum (zero padded)
//   horizontal: [a, 1, a] / (3*(1+2a)),  a = exp(-1/s^2), s = 3*std[b]
//
// R6 = R3 (best: 2 rows/iter, register row window, smem vsum exchange,
// 2 LDG.128 in flight) + __launch_bounds__(384,5) forcing regs<=34 so 5
// blocks/SM co-reside (60 warps, 93.75% theoretical occupancy vs 75%).
// Addressing converted to pointer increments to help ptxas fit the budget.

#define H       512
#define ROWW    1536            // 512 * 3 floats per image row
#define NT      384             // 384 threads x float4 = one row
#define RPB     32              // rows per block band
#define PAD     4               // float halo each side (one float4)
#define SROW    (ROWW + 2 * PAD)

__global__ __launch_bounds__(NT, 5)
void gauss_blur_kernel(const float* __restrict__ x,
                       const float* __restrict__ stds,
                       float* __restrict__ out)
{
    __shared__ float vs[4][SROW];

    const int b  = blockIdx.y;
    const int i0 = blockIdx.x * RPB;
    const int t  = threadIdx.x;

    // zero halos of all 4 buffers (threads 0..15: buf = t/4, idx = t%4)
    if (t < 16) {
        const int buf = t >> 2, idx = t & 3;
        vs[buf][idx] = 0.0f;
        vs[buf][ROWW + PAD + idx] = 0.0f;
    }

    const float s   = stds[b] * 3.0f;
    const float a   = expf(-1.0f / (s * s));
    const float inv = 1.0f / (3.0f * (1.0f + 2.0f * a));

    // Rolling global pointers (chunk t of each row), advanced by ROWW floats.
    const float4* gin  = reinterpret_cast<const float4*>(
                             x + ((size_t)b * H + i0) * ROWW) + t;   // row i0
    float4*       gout = reinterpret_cast<float4*>(
                             out + ((size_t)b * H + i0) * ROWW) + t; // row i0
    const int CHUNKS_PER_ROW = ROWW / 4;

    const float4 Z = make_float4(0.0f, 0.0f, 0.0f, 0.0f);

    // rolling window: rm=row gi-1, rc=gi, rp=gi+1, rq=gi+2
    // i0 is a multiple of 32: i0-1 valid iff blockIdx.x>0; i0+1,i0+2 always valid.
    float4 rm = (i0 > 0) ? gin[-CHUNKS_PER_ROW] : Z;
    float4 rc = gin[0];
    float4 rp = gin[CHUNKS_PER_ROW];
    float4 rq = gin[2 * CHUNKS_PER_ROW];
    gin += 3 * CHUNKS_PER_ROW;   // -> row gi+3

    const bool lastband = (i0 + RPB >= H);

    int par = 0;
    #pragma unroll 1
    for (int r = 0; r < RPB; r += 2) {
        // prefetch rows gi+3, gi+4 (zeros past the image end, last band only)
        float4 ra, rb;
        if (lastband && r >= RPB - 4) {
            const int gi = i0 + r;
            ra = (gi + 3 < H) ? gin[0] : Z;
            rb = (gi + 4 < H) ? gin[CHUNKS_PER_ROW] : Z;
        } else {
            ra = gin[0];
            rb = gin[CHUNKS_PER_ROW];
        }
        gin += 2 * CHUNKS_PER_ROW;

        // vertical sums for output rows gi and gi+1
        float4 v0, v1;
        v0.x = rm.x + rc.x + rp.x;  v1.x = rc.x + rp.x + rq.x;
        v0.y = rm.y + rc.y + rp.y;  v1.y = rc.y + rp.y + rq.y;
        v0.z = rm.z + rc.z + rp.z;  v1.z = rc.z + rp.z + rq.z;
        v0.w = rm.w + rc.w + rp.w;  v1.w = rc.w + rp.w + rq.w;

        float* s0 = vs[par * 2];
        float* s1 = vs[par * 2 + 1];
        reinterpret_cast<float4*>(s0 + PAD)[t] = v0;
        reinterpret_cast<float4*>(s1 + PAD)[t] = v1;
        __syncthreads();

        // neighbor chunks (16B aligned): L = vsum[4t-4..4t-1], R = vsum[4t+4..4t+7]
        const float4 L0 = reinterpret_cast<const float4*>(s0)[t];
        const float4 R0 = reinterpret_cast<const float4*>(s0 + PAD + 4)[t];
        const float4 L1 = reinterpret_cast<const float4*>(s1)[t];
        const float4 R1 = reinterpret_cast<const float4*>(s1 + PAD + 4)[t];

        // out[e] = inv * (a*(vsum[e-3] + vsum[e+3]) + vsum[e]),  e = 4t+j
        float4 o0, o1;
        o0.x = inv * (a * (L0.y + v0.w) + v0.x);
        o0.y = inv * (a * (L0.z + R0.x) + v0.y);
        o0.z = inv * (a * (L0.w + R0.y) + v0.z);
        o0.w = inv * (a * (v0.x + R0.z) + v0.w);

        o1.x = inv * (a * (L1.y + v1.w) + v1.x);
        o1.y = inv * (a * (L1.z + R1.x) + v1.y);
        o1.z = inv * (a * (L1.w + R1.y) + v1.z);
        o1.w = inv * (a * (v1.x + R1.z) + v1.w);

        __stcs(gout, o0);
        __stcs(gout + CHUNKS_PER_ROW, o1);
        gout += 2 * CHUNKS_PER_ROW;

        // rotate window by 2 rows; flip smem buffer pair
        rm = rp; rc = rq; rp = ra; rq = rb;
        par ^= 1;
    }
}

extern "C" void kernel_launch(void* const* d_in, const int* in_sizes, int n_in,
                              void* d_out, int out_size)
{
    const float* x    = (const float*)d_in[0];
    const float* stds = (const float*)d_in[1];
    float* out        = (float*)d_out;

    dim3 grid(H / RPB, 64);   // (16, 64) = 1024 blocks
    gauss_blur_kernel<<<grid, NT>>>(x, stds, out);
}

// round 7
// speedup vs baseline: 1.3222x; 1.3222x over previous
#include <cuda_runtime.h>
#include <cuda_bf16.h>
#include <cstdint>

// AddingGaussianBlur: x (64,512,512,3) f32, stds (64,) f32 -> out f32.
//
// Separable (reference's 3x3 kernel depends only on column index):
//   vertical  : unweighted 3-row sum (zero padded)
//   horizontal: [a, 1, a] / (3*(1+2a)),  a = exp(-1/s^2), s = 3*std[b]
//
// R7: cp.async row pipeline. Thread t streams its 16B chunk of each row into
// a 4-slot smem ring (3 rows in flight, zero register cost -> MLP decoupled
// from occupancy). Ring is thread-private (chunk t written & read only by
// thread t) so only the vsum +-3 exchange needs a barrier (1/row, double
// buffered). Vertical window rolls in registers as in R3.

#define H       512
#define ROWW    1536            // 512 * 3 floats per image row
#define NT      384             // 384 threads x float4 = one row
#define RPB     32              // rows per block band
#define DEP     3               // rows in flight (cp.async groups pending)
#define NSLOT   4               // ring slots (power of 2, >= DEP+1)
#define PAD     4               // float halo each side of vsum row
#define SROW    (ROWW + 2 * PAD)

__global__ __launch_bounds__(NT)
void gauss_blur_kernel(const float* __restrict__ x,
                       const float* __restrict__ stds,
                       float* __restrict__ out)
{
    __shared__ __align__(16) float ring[NSLOT][ROWW];
    __shared__ __align__(16) float vs[2][SROW];

    const int b  = blockIdx.y;
    const int i0 = blockIdx.x * RPB;
    const int t  = threadIdx.x;

    // zero vsum halos once (visible after first __syncthreads)
    if (t < 8) {
        const int buf = t >> 2, idx = t & 3;
        vs[buf][idx] = 0.0f;
        vs[buf][ROWW + PAD + idx] = 0.0f;
    }

    const float s   = stds[b] * 3.0f;
    const float a   = expf(-1.0f / (s * s));
    const float inv = 1.0f / (3.0f * (1.0f + 2.0f * a));

    const float* __restrict__ xb = x   + (size_t)b * H * ROWW;
    float*       __restrict__ ob = out + (size_t)b * H * ROWW;

    const uint32_t ring_smem = (uint32_t)__cvta_generic_to_shared(&ring[0][0]) + t * 16u;
    const float4 Z = make_float4(0.0f, 0.0f, 0.0f, 0.0f);

    // Issue one row into the ring: cp.async if in range, STS zeros otherwise.
    // Always commits a group so wait_group counts stay static.
    auto issue = [&](int gi) {
        const int slot = (gi - i0 + 1) & (NSLOT - 1);
        if ((unsigned)gi < (unsigned)H) {
            const float* src = xb + (size_t)gi * ROWW + t * 4;
            const uint32_t dst = ring_smem + slot * (ROWW * 4);
            asm volatile("cp.async.ca.shared.global [%0], [%1], 16;\n"
                         :: "r"(dst), "l"(src));
        } else {
            reinterpret_cast<float4*>(ring[slot] + t * 4)[0] = Z;
        }
        asm volatile("cp.async.commit_group;\n");
    };

    // Prologue: rows i0-1 .. i0+DEP-1 (DEP+1 groups), then drain to 2 pending
    // so rows i0-1 and i0 are resident.
    issue(i0 - 1);
    issue(i0);
    issue(i0 + 1);
    issue(i0 + 2);
    asm volatile("cp.async.wait_group 2;\n");

    float4 rm = reinterpret_cast<const float4*>(ring[0] + t * 4)[0];  // row i0-1
    float4 rc = reinterpret_cast<const float4*>(ring[1] + t * 4)[0];  // row i0

    int par = 0;
    #pragma unroll 1
    for (int r = 0; r < RPB; r++) {
        const int gi = i0 + r;

        // keep DEP rows in flight
        issue(gi + DEP);
        // rows <= gi+1 complete (pending: gi+2, gi+3)
        asm volatile("cp.async.wait_group 2;\n");

        const int slot = (r + 2) & (NSLOT - 1);   // row gi+1
        const float4 rp = reinterpret_cast<const float4*>(ring[slot] + t * 4)[0];

        // vertical sum
        float4 v;
        v.x = rm.x + rc.x + rp.x;
        v.y = rm.y + rc.y + rp.y;
        v.z = rm.z + rc.z + rp.z;
        v.w = rm.w + rc.w + rp.w;

        float* sv = vs[par];
        reinterpret_cast<float4*>(sv + PAD)[t] = v;
        __syncthreads();

        // neighbor chunks (16B aligned): L = vsum[4t-4..4t-1], R = vsum[4t+4..4t+7]
        const float4 L = reinterpret_cast<const float4*>(sv)[t];
        const float4 R = reinterpret_cast<const float4*>(sv + PAD + 4)[t];

        // out[e] = inv * (a*(vsum[e-3] + vsum[e+3]) + vsum[e]),  e = 4t+j
        float4 o;
        o.x = inv * (a * (L.y + v.w) + v.x);
        o.y = inv * (a * (L.z + R.x) + v.y);
        o.z = inv * (a * (L.w + R.y) + v.z);
        o.w = inv * (a * (v.x + R.z) + v.w);

        __stcs(&reinterpret_cast<float4*>(ob + (size_t)gi * ROWW)[t], o);

        // rotate window; flip vsum buffer (reuse of vs[par] two iterations
        // later is ordered by the interleaving __syncthreads)
        rm = rc; rc = rp;
        par ^= 1;
    }
}

extern "C" void kernel_launch(void* const* d_in, const int* in_sizes, int n_in,
                              void* d_out, int out_size)
{
    const float* x    = (const float*)d_in[0];
    const float* stds = (const float*)d_in[1];
    float* out        = (float*)d_out;

    dim3 grid(H / RPB, 64);   // (16, 64) = 1024 blocks
    gauss_blur_kernel<<<grid, NT>>>(x, stds, out);
}